// round 13
// baseline (speedup 1.0000x reference)
#include <cuda_runtime.h>
#include <cuda_bf16.h>
#include <math.h>
#include <stdint.h>

#define TPB    512
#define MROWS  64
#define HID    192
#define TSTEPS 20
#define NBATCH 131072
#define NCH    24        // gate chunks of 32
#define KSH    6         // ksteps per K-half (12 total)
#define ASTR   400       // A/B row stride in bytes (200 bf16) -> conflict-free ldmatrix
#define CSTRN  193       // c row stride in floats
#define RSTR   33        // reduction row stride in floats (scalar access only!)

// SMEM byte offsets
#define A_OFF    0       // [par=2][term=2][64 rows][ASTR]
#define APAR     51200
#define ATERM    25600
#define B_OFF    102400  // [stage=2][term=2][32 n][ASTR]
#define BSTAGE   25600
#define BTERM    12800
#define RED_OFF  153600  // [kg=2][64][RSTR] f32 = 16896
#define C_OFF    170496  // [64][CSTRN] f32 = 49408
#define WIH_OFF  219904  // [768][2] f32
#define BIAS_OFF 226048  // [768] f32
#define WOUT_OFF 229120  // [2][192] f32
#define X_OFF    230656  // [64][2] f32
#define SMEM_BYTES 231168

// prepacked B: [24 chunks][2 terms][32 n][200 k] bf16 (term0=hi, term1=lo)
__device__ uint4 g_bpack[38400];   // 614400 B

// ---------------- helpers ----------------
__device__ __forceinline__ uint32_t smem_u32(const void* p) {
    uint32_t a;
    asm("{ .reg .u64 t; cvta.to.shared.u64 t, %1; cvt.u32.u64 %0, t; }"
        : "=r"(a) : "l"(p));
    return a;
}
__device__ __forceinline__ void ldmx4(uint32_t* r, uint32_t addr) {
    asm volatile("ldmatrix.sync.aligned.m8n8.x4.shared.b16 {%0,%1,%2,%3}, [%4];"
                 : "=r"(r[0]), "=r"(r[1]), "=r"(r[2]), "=r"(r[3]) : "r"(addr));
}
__device__ __forceinline__ void mma16816(float* c, const uint32_t* a,
                                         uint32_t b0, uint32_t b1) {
    asm volatile(
        "mma.sync.aligned.m16n8k16.row.col.f32.bf16.bf16.f32 "
        "{%0,%1,%2,%3}, {%4,%5,%6,%7}, {%8,%9}, {%0,%1,%2,%3};"
        : "+f"(c[0]), "+f"(c[1]), "+f"(c[2]), "+f"(c[3])
        : "r"(a[0]), "r"(a[1]), "r"(a[2]), "r"(a[3]), "r"(b0), "r"(b1));
}
__device__ __forceinline__ void cpasync16(uint32_t dst, const void* src) {
    asm volatile("cp.async.cg.shared.global [%0], [%1], 16;"
                 :: "r"(dst), "l"(src));
}
__device__ __forceinline__ float sigmoidf_(float x) {
    float e = __expf(-x);
    return __fdividef(1.f, 1.f + e);
}
__device__ __forceinline__ float tanhf_(float x) {
    float ax = fabsf(x);
    float e  = __expf(-2.f * ax);
    float r  = (1.f - e) * __fdividef(1.f, 1.f + e);
    return copysignf(r, x);
}

// ---------------- prepack: w_hh -> unit-paired hi/lo bf16 tiles ----------------
// Column n (0..31) of chunk cc: U = cc*8 + (n>>4)*4 + ((n&7)>>1),
// g = (n&1) + 2*((n>>3)&1), grow = g*192 + U.
__global__ void prepack(const float* __restrict__ w_hh) {
    const int e   = blockIdx.x * 256 + threadIdx.x;    // 1200 blocks -> 307200
    const int k   = e % 200;
    const int n   = (e / 200) & 31;
    const int cc  = e / 12800;
    const int np  = n & 15;
    const int U   = cc * 8 + (n >> 4) * 4 + ((np & 7) >> 1);
    const int g   = (np & 1) + 2 * (np >> 3);
    const int grow = g * HID + U;
    const float v = (k < HID) ? w_hh[(size_t)grow * HID + k] : 0.f;
    const __nv_bfloat16 hi = __float2bfloat16(v);
    const int term = (e / 6400) & 1;
    ((__nv_bfloat16*)g_bpack)[e] =
        term ? __float2bfloat16(v - __bfloat162float(hi)) : hi;
}

// ---------------- main kernel ----------------
__global__ void __launch_bounds__(TPB, 1)
lstm_mma(const float* __restrict__ obs,    // [20][N][2]
         const float* __restrict__ h0,     // [N][192]
         const float* __restrict__ w_ih,   // [768][2]
         const float* __restrict__ b_ih,   // [768]
         const float* __restrict__ b_hh,   // [768]
         const float* __restrict__ w_out,  // [2][192]
         const float* __restrict__ b_out,  // [2]
         float* __restrict__ out)          // [20][N][2]
{
    extern __shared__ char sm[];
    const uint32_t smb = smem_u32(sm);
    float* red_s  = (float*)(sm + RED_OFF);
    float* c_s    = (float*)(sm + C_OFF);
    float* wih_s  = (float*)(sm + WIH_OFF);
    float* bias_s = (float*)(sm + BIAS_OFF);
    float* wout_s = (float*)(sm + WOUT_OFF);
    float* x_s    = (float*)(sm + X_OFF);

    const int tid  = threadIdx.x;
    const int lane = tid & 31;
    const int wid  = tid >> 5;
    const int rg   = wid & 3;              // rowgroup: rows rg*16..+15
    const int cg   = (wid >> 2) & 1;       // colgroup within 32-col chunk
    const int kg   = wid >> 3;             // K-half (0: k0..95, 1: k96..191)
    const size_t rowg = (size_t)blockIdx.x * MROWS;

    // ---- one-time staging ----
    for (int i = tid; i < MROWS * HID; i += TPB) {       // h0 -> A[par=0] hi/lo
        const int r = i / HID, k = i - r * HID;
        const float v = h0[(rowg + r) * HID + k];
        const __nv_bfloat16 hi = __float2bfloat16(v);
        const __nv_bfloat16 lo = __float2bfloat16(v - __bfloat162float(hi));
        *(__nv_bfloat16*)(sm + A_OFF + r * ASTR + k * 2) = hi;
        *(__nv_bfloat16*)(sm + A_OFF + ATERM + r * ASTR + k * 2) = lo;
    }
    for (int i = tid; i < MROWS * CSTRN; i += TPB) c_s[i] = 0.f;
    for (int i = tid; i < 768; i += TPB) {
        wih_s[2 * i]     = w_ih[2 * i];
        wih_s[2 * i + 1] = w_ih[2 * i + 1];
        bias_s[i]        = b_ih[i] + b_hh[i];
    }
    for (int i = tid; i < 384; i += TPB) wout_s[i] = w_out[i];
    if (tid < 128) x_s[tid] = obs[rowg * 2 + tid];       // t=0 uses obs[0]

    // prefetch chunk 0 -> stage 0
    {
        const uint4* src = g_bpack;
        const uint32_t dst = smb + B_OFF;
        for (int i = tid; i < 1600; i += TPB) cpasync16(dst + i * 16, src + i);
        asm volatile("cp.async.commit_group;" ::: "memory");
    }

    // order cooperative staging before any A-fragment reads (step-0 race fix)
    __syncthreads();

    // per-lane ldmatrix offsets (bytes); kg selects the K-half (6*32 = 192 B)
    const uint32_t a_lane_off =
        (uint32_t)((rg * 16 + (lane & 7) + ((lane >> 3) & 1) * 8) * ASTR
                   + ((lane >> 4) & 1) * 16 + kg * 192);
    const uint32_t b_lane_off =
        (uint32_t)((cg * 16 + ((lane >> 4) & 1) * 8 + (lane & 7)) * ASTR
                   + ((lane >> 3) & 1) * 16 + kg * 192);
    const int ulan = lane & 3;             // unit-within-4 this thread owns
    const int r0   = rg * 16 + (lane >> 2);
    const int cb   = cg * 16 + ulan * 2;   // reduction column base

    // epilogue mapping: thread -> (row, unit-in-chunk)
    const int er  = tid & 63;              // row
    const int eu8 = tid >> 6;              // unit 0..7 within chunk
    const int enb = (eu8 >> 2) * 16 + (eu8 & 3) * 2;   // i/f column base

    for (int t = 0; t < TSTEPS; t++) {
        const int par = t & 1;

        // ---- persistent A fragments for this step (this warp's K-half) ----
        const uint32_t a_hi = smb + A_OFF + par * APAR + a_lane_off;
        uint32_t afh[KSH][4], afl[KSH][4];
#pragma unroll
        for (int j = 0; j < KSH; j++) {
            ldmx4(afh[j], a_hi + j * 32);
            ldmx4(afl[j], a_hi + ATERM + j * 32);
        }

        char* an_hi = sm + A_OFF + (par ^ 1) * APAR;   // h_new destination
        char* an_lo = an_hi + ATERM;

#pragma unroll 1
        for (int cc = 0; cc < NCH; cc++) {
            asm volatile("cp.async.wait_group 0;" ::: "memory");
            __syncthreads();   // B stage ready; red buffer reusable; x_s visible

            // prefetch next chunk into the other stage
            {
                const int nc = (cc + 1 == NCH) ? 0 : cc + 1;
                const uint4* src = g_bpack + nc * 1600;
                const uint32_t dst = smb + B_OFF + ((cc + 1) & 1) * BSTAGE;
                for (int i = tid; i < 1600; i += TPB) cpasync16(dst + i * 16, src + i);
                asm volatile("cp.async.commit_group;" ::: "memory");
            }

            // accumulator init: kg0 carries bias + x@w_ih^T; kg1 starts at 0
            const int U = cc * 8 + cg * 4 + ulan;
            float dA0[4], dA1[4], dB0[4], dB1[4];
#pragma unroll
            for (int j = 0; j < 4; j++) { dA0[j]=0.f; dA1[j]=0.f; dB0[j]=0.f; dB1[j]=0.f; }
            if (kg == 0) {
                const float x00 = x_s[r0 * 2],       x01 = x_s[r0 * 2 + 1];
                const float x10 = x_s[(r0 + 8) * 2], x11 = x_s[(r0 + 8) * 2 + 1];
#pragma unroll
                for (int g = 0; g < 2; g++) {
                    const int grow = g * HID + U;
                    const float w0 = wih_s[2 * grow], w1 = wih_s[2 * grow + 1];
                    const float bb = bias_s[grow];
                    dA0[g]     = fmaf(x00, w0, fmaf(x01, w1, bb));
                    dA0[g + 2] = fmaf(x10, w0, fmaf(x11, w1, bb));
                }
#pragma unroll
                for (int g = 0; g < 2; g++) {
                    const int grow = (g + 2) * HID + U;
                    const float w0 = wih_s[2 * grow], w1 = wih_s[2 * grow + 1];
                    const float bb = bias_s[grow];
                    dA1[g]     = fmaf(x00, w0, fmaf(x01, w1, bb));
                    dA1[g + 2] = fmaf(x10, w0, fmaf(x11, w1, bb));
                }
            }

            // K sweep over this warp's half: B-only ldmatrix
            const uint32_t bb0 = smb + B_OFF + (cc & 1) * BSTAGE + b_lane_off;
#pragma unroll
            for (int j = 0; j < KSH; j++) {
                uint32_t bh[4], bl[4];
                ldmx4(bh, bb0 + j * 32);
                ldmx4(bl, bb0 + BTERM + j * 32);
                mma16816(dA0, afh[j], bh[0], bh[1]);
                mma16816(dA1, afh[j], bh[2], bh[3]);
                mma16816(dB0, afh[j], bl[0], bl[1]);
                mma16816(dB1, afh[j], bl[2], bl[3]);
                mma16816(dA0, afl[j], bh[0], bh[1]);
                mma16816(dA1, afl[j], bh[2], bh[3]);
            }

            // merge chains -> reduction buffer (SCALAR stores: RSTR is odd,
            // so 8-byte accesses would be misaligned — round-12 bug)
            {
                float* rp = red_s + kg * (MROWS * RSTR);
                float* q0 = rp + r0 * RSTR + cb;
                float* q1 = rp + (r0 + 8) * RSTR + cb;
                q0[0] = dA0[0] + dB0[0];  q0[1] = dA0[1] + dB0[1];
                q1[0] = dA0[2] + dB0[2];  q1[1] = dA0[3] + dB0[3];
                q0[8] = dA1[0] + dB1[0];  q0[9] = dA1[1] + dB1[1];
                q1[8] = dA1[2] + dB1[2];  q1[9] = dA1[3] + dB1[3];
            }
            __syncthreads();   // partials complete

            // epilogue: one (row, unit) pair per thread (scalar, conflict-free:
            // er*33 mod 32 = er -> 32 distinct banks per warp)
            {
                const float* rp0 = red_s + er * RSTR + enb;
                const float* rp1 = rp0 + MROWS * RSTR;
                const float iv = sigmoidf_(rp0[0] + rp1[0]);
                const float fv = sigmoidf_(rp0[1] + rp1[1]);
                const float gv = tanhf_(rp0[8] + rp1[8]);
                const float ov = sigmoidf_(rp0[9] + rp1[9]);
                const int Ue = cc * 8 + eu8;
                const float cn = fmaf(fv, c_s[er * CSTRN + Ue], iv * gv);
                c_s[er * CSTRN + Ue] = cn;
                const float hv = ov * tanhf_(cn);
                const __nv_bfloat16 hhi = __float2bfloat16(hv);
                const __nv_bfloat16 hlo =
                    __float2bfloat16(hv - __bfloat162float(hhi));
                *(__nv_bfloat16*)(an_hi + er * ASTR + Ue * 2) = hhi;
                *(__nv_bfloat16*)(an_lo + er * ASTR + Ue * 2) = hlo;
            }
            // red-buffer reuse + B-stage reuse protected by next chunk's barrier
        } // cc

        __syncthreads();   // h_new (A[par^1]) complete

        if (tid < 256) {
            // out[t] = h_t @ w_out^T + b_out ; K split 2-way + shfl reduce
            const int r = tid >> 2, comp = (tid >> 1) & 1, kh = tid & 1;
            const __nv_bfloat162* ph =
                (const __nv_bfloat162*)(an_hi + r * ASTR) + kh * 48;
            const __nv_bfloat162* pl =
                (const __nv_bfloat162*)(an_lo + r * ASTR) + kh * 48;
            const float* wp = wout_s + comp * HID + kh * 96;
            float s0 = 0.f, s1 = 0.f;
#pragma unroll 4
            for (int u2 = 0; u2 < 48; u2++) {
                const float2 hh = __bfloat1622float2(ph[u2]);
                const float2 ll = __bfloat1622float2(pl[u2]);
                s0 = fmaf(hh.x + ll.x, wp[2 * u2],     s0);
                s1 = fmaf(hh.y + ll.y, wp[2 * u2 + 1], s1);
            }
            float s = s0 + s1;
            s += __shfl_xor_sync(0xFFFFFFFFu, s, 1);
            if (kh == 0)
                out[((size_t)t * NBATCH + rowg + r) * 2 + comp] = s + b_out[comp];
        } else if (tid >= 384) {
            // stage x for step t+1 (xs index = t); extra load at t=19 harmless
            x_s[tid - 384] = obs[((size_t)t * NBATCH + rowg) * 2 + (tid - 384)];
        }
        // x_s / buffer visibility for next step covered by chunk-0 top barrier
    } // t
}

extern "C" void kernel_launch(void* const* d_in, const int* in_sizes, int n_in,
                              void* d_out, int out_size)
{
    const float* obs   = (const float*)d_in[0];
    const float* h0    = (const float*)d_in[1];
    const float* w_ih  = (const float*)d_in[2];
    const float* w_hh  = (const float*)d_in[3];
    const float* b_ih  = (const float*)d_in[4];
    const float* b_hh  = (const float*)d_in[5];
    const float* w_out = (const float*)d_in[6];
    const float* b_out = (const float*)d_in[7];
    float* out = (float*)d_out;

    prepack<<<1200, 256>>>(w_hh);

    cudaFuncSetAttribute(lstm_mma, cudaFuncAttributeMaxDynamicSharedMemorySize,
                         SMEM_BYTES);
    lstm_mma<<<NBATCH / MROWS, TPB, SMEM_BYTES>>>(obs, h0, w_ih, b_ih, b_hh,
                                                  w_out, b_out, out);
}

// round 14
// speedup vs baseline: 1.2937x; 1.2937x over previous
#include <cuda_runtime.h>
#include <cuda_fp16.h>
#include <math.h>
#include <stdint.h>

#define TPB    256
#define MROWS  64
#define HID    192
#define TSTEPS 20
#define NBATCH 131072
#define NCH    24        // gate chunks of 32
#define KSTEPS 12
#define ASTR   400       // A/B row stride in bytes (200 fp16) -> conflict-free ldmatrix
#define CSTRN  193       // c / h32 row stride in floats (scalar access only)

// SMEM byte offsets
#define A_OFF    0       // A: [par=2][64 rows][ASTR] fp16 (single term)
#define APAR     25600
#define B_OFF    51200   // [stage=2][term=2][32 n][ASTR] fp16
#define BSTAGE   25600
#define BTERM    12800
#define H32_OFF  102400  // h fp32: [64][CSTRN] = 49408
#define C_OFF    151808  // c: [64][CSTRN] f32 = 49408
#define WIH_OFF  201216  // [768][2] f32
#define BIAS_OFF 207360  // [768] f32
#define WOUT_OFF 210432  // [2][192] f32
#define X_OFF    211968  // [64][2] f32
#define SMEM_BYTES 212480

// prepacked B: [24 chunks][2 terms][32 n][200 k] fp16 (term0=hi, term1=lo)
__device__ uint4 g_bpack[38400];   // 614400 B

// ---------------- helpers ----------------
__device__ __forceinline__ uint32_t smem_u32(const void* p) {
    uint32_t a;
    asm("{ .reg .u64 t; cvta.to.shared.u64 t, %1; cvt.u32.u64 %0, t; }"
        : "=r"(a) : "l"(p));
    return a;
}
__device__ __forceinline__ void ldmx4(uint32_t* r, uint32_t addr) {
    asm volatile("ldmatrix.sync.aligned.m8n8.x4.shared.b16 {%0,%1,%2,%3}, [%4];"
                 : "=r"(r[0]), "=r"(r[1]), "=r"(r[2]), "=r"(r[3]) : "r"(addr));
}
__device__ __forceinline__ void mma16816(float* c, const uint32_t* a,
                                         uint32_t b0, uint32_t b1) {
    asm volatile(
        "mma.sync.aligned.m16n8k16.row.col.f32.f16.f16.f32 "
        "{%0,%1,%2,%3}, {%4,%5,%6,%7}, {%8,%9}, {%0,%1,%2,%3};"
        : "+f"(c[0]), "+f"(c[1]), "+f"(c[2]), "+f"(c[3])
        : "r"(a[0]), "r"(a[1]), "r"(a[2]), "r"(a[3]), "r"(b0), "r"(b1));
}
__device__ __forceinline__ void cpasync16(uint32_t dst, const void* src) {
    asm volatile("cp.async.cg.shared.global [%0], [%1], 16;"
                 :: "r"(dst), "l"(src));
}
__device__ __forceinline__ float sigmoidf_(float x) {
    float e = __expf(-x);
    return __fdividef(1.f, 1.f + e);
}
__device__ __forceinline__ float tanhf_(float x) {
    float ax = fabsf(x);
    float e  = __expf(-2.f * ax);
    float r  = (1.f - e) * __fdividef(1.f, 1.f + e);
    return copysignf(r, x);
}

// ---------------- prepack: w_hh -> unit-paired fp16 hi/lo tiles ----------------
// Column n (0..31) of chunk cc: U = cc*8 + (n>>4)*4 + ((n&7)>>1),
// g = (n&1) + 2*((n>>3)&1), grow = g*192 + U.  (mapping unchanged from r11)
__global__ void prepack(const float* __restrict__ w_hh) {
    const int e   = blockIdx.x * 256 + threadIdx.x;    // 1200 blocks -> 307200
    const int k   = e % 200;
    const int n   = (e / 200) & 31;
    const int cc  = e / 12800;
    const int np  = n & 15;
    const int U   = cc * 8 + (n >> 4) * 4 + ((np & 7) >> 1);
    const int g   = (np & 1) + 2 * (np >> 3);
    const int grow = g * HID + U;
    const float v = (k < HID) ? w_hh[(size_t)grow * HID + k] : 0.f;
    const __half hi = __float2half(v);
    const int term = (e / 6400) & 1;
    ((__half*)g_bpack)[e] = term ? __float2half(v - __half2float(hi)) : hi;
}

// ---------------- main kernel ----------------
__global__ void __launch_bounds__(TPB, 1)
lstm_mma(const float* __restrict__ obs,    // [20][N][2]
         const float* __restrict__ h0,     // [N][192]
         const float* __restrict__ w_ih,   // [768][2]
         const float* __restrict__ b_ih,   // [768]
         const float* __restrict__ b_hh,   // [768]
         const float* __restrict__ w_out,  // [2][192]
         const float* __restrict__ b_out,  // [2]
         float* __restrict__ out)          // [20][N][2]
{
    extern __shared__ char sm[];
    const uint32_t smb = smem_u32(sm);
    float* h32_s  = (float*)(sm + H32_OFF);
    float* c_s    = (float*)(sm + C_OFF);
    float* wih_s  = (float*)(sm + WIH_OFF);
    float* bias_s = (float*)(sm + BIAS_OFF);
    float* wout_s = (float*)(sm + WOUT_OFF);
    float* x_s    = (float*)(sm + X_OFF);

    const int tid  = threadIdx.x;
    const int lane = tid & 31;
    const int wid  = tid >> 5;
    const int rg   = wid & 3;              // rowgroup: rows rg*16..+15
    const int cg   = wid >> 2;             // colgroup within 32-col chunk
    const size_t rowg = (size_t)blockIdx.x * MROWS;

    // ---- one-time staging ----
    for (int i = tid; i < MROWS * HID; i += TPB) {       // h0 -> A[par=0] fp16
        const int r = i / HID, k = i - r * HID;
        *(__half*)(sm + A_OFF + r * ASTR + k * 2) = __float2half(h0[(rowg + r) * HID + k]);
    }
    for (int i = tid; i < MROWS * CSTRN; i += TPB) c_s[i] = 0.f;
    for (int i = tid; i < 768; i += TPB) {
        wih_s[2 * i]     = w_ih[2 * i];
        wih_s[2 * i + 1] = w_ih[2 * i + 1];
        bias_s[i]        = b_ih[i] + b_hh[i];
    }
    for (int i = tid; i < 384; i += TPB) wout_s[i] = w_out[i];
    if (tid < 128) x_s[tid] = obs[rowg * 2 + tid];       // t=0 uses obs[0]
    const float boutv = (tid < 128) ? b_out[tid & 1] : 0.f;

    // prefetch chunk 0 -> stage 0
    {
        const uint4* src = g_bpack;
        const uint32_t dst = smb + B_OFF;
        for (int i = tid; i < 1600; i += TPB) cpasync16(dst + i * 16, src + i);
        asm volatile("cp.async.commit_group;" ::: "memory");
    }

    // order cooperative staging before any A-fragment reads (step-0 race fix)
    __syncthreads();

    // per-lane ldmatrix offsets (bytes)
    const uint32_t a_lane_off =
        (uint32_t)((rg * 16 + (lane & 7) + ((lane >> 3) & 1) * 8) * ASTR
                   + ((lane >> 4) & 1) * 16);
    const uint32_t b_lane_off =
        (uint32_t)((cg * 16 + ((lane >> 4) & 1) * 8 + (lane & 7)) * ASTR
                   + ((lane >> 3) & 1) * 16);
    const int ulan = lane & 3;             // unit-within-4 this thread owns
    const int r0   = rg * 16 + (lane >> 2);

    const float* wout0 = wout_s + (tid & 1) * HID;   // for out-projection
    const int opr = tid >> 1;                        // out-projection row

    for (int t = 0; t < TSTEPS; t++) {
        const int par = t & 1;

        // ---- persistent A fragments for this step (single fp16 term) ----
        const uint32_t a_p = smb + A_OFF + par * APAR + a_lane_off;
        uint32_t af[KSTEPS][4];
#pragma unroll
        for (int ks = 0; ks < KSTEPS; ks++) ldmx4(af[ks], a_p + ks * 32);

        char* an = sm + A_OFF + (par ^ 1) * APAR;   // h_new fp16 destination

#pragma unroll 1
        for (int cc = 0; cc < NCH; cc++) {
            asm volatile("cp.async.wait_group 0;" ::: "memory");
            __syncthreads();   // stage (cc&1) ready; x_s visible (chunk 0)

            // prefetch next chunk into the other stage
            {
                const int nc = (cc + 1 == NCH) ? 0 : cc + 1;
                const uint4* src = g_bpack + nc * 1600;
                const uint32_t dst = smb + B_OFF + ((cc + 1) & 1) * BSTAGE;
                for (int i = tid; i < 1600; i += TPB) cpasync16(dst + i * 16, src + i);
                asm volatile("cp.async.commit_group;" ::: "memory");
            }

            // accumulator init: dH = bias + x@w_ih^T (hi chain), dL = 0 (lo chain)
            const int U = cc * 8 + cg * 4 + ulan;
            float dH0[4], dH1[4], dL0[4], dL1[4];
            {
                const float x00 = x_s[r0 * 2],       x01 = x_s[r0 * 2 + 1];
                const float x10 = x_s[(r0 + 8) * 2], x11 = x_s[(r0 + 8) * 2 + 1];
#pragma unroll
                for (int g = 0; g < 2; g++) {
                    const int grow = g * HID + U;
                    const float w0 = wih_s[2 * grow], w1 = wih_s[2 * grow + 1];
                    const float bb = bias_s[grow];
                    dH0[g]     = fmaf(x00, w0, fmaf(x01, w1, bb));
                    dH0[g + 2] = fmaf(x10, w0, fmaf(x11, w1, bb));
                }
#pragma unroll
                for (int g = 0; g < 2; g++) {
                    const int grow = (g + 2) * HID + U;
                    const float w0 = wih_s[2 * grow], w1 = wih_s[2 * grow + 1];
                    const float bb = bias_s[grow];
                    dH1[g]     = fmaf(x00, w0, fmaf(x01, w1, bb));
                    dH1[g + 2] = fmaf(x10, w0, fmaf(x11, w1, bb));
                }
#pragma unroll
                for (int j = 0; j < 4; j++) { dL0[j] = 0.f; dL1[j] = 0.f; }
            }

            // K sweep: 2-term fp16 (A * B_hi) + (A * B_lo); 4 independent chains
            const uint32_t bb0 = smb + B_OFF + (cc & 1) * BSTAGE + b_lane_off;
#pragma unroll
            for (int ks = 0; ks < KSTEPS; ks++) {
                uint32_t bh[4], bl[4];
                ldmx4(bh, bb0 + ks * 32);
                ldmx4(bl, bb0 + BTERM + ks * 32);
                mma16816(dH0, af[ks], bh[0], bh[1]);   // hi, cols 0-7
                mma16816(dH1, af[ks], bh[2], bh[3]);   // hi, cols 8-15
                mma16816(dL0, af[ks], bl[0], bl[1]);   // lo, cols 0-7
                mma16816(dL1, af[ks], bl[2], bl[3]);   // lo, cols 8-15
            }

            // epilogue: thread owns unit U at rows r0 and r0+8
#pragma unroll
            for (int rr = 0; rr < 2; rr++) {
                const int r = r0 + rr * 8;
                const float iv = sigmoidf_(dH0[rr * 2 + 0] + dL0[rr * 2 + 0]);
                const float fv = sigmoidf_(dH0[rr * 2 + 1] + dL0[rr * 2 + 1]);
                const float gv = tanhf_(dH1[rr * 2 + 0] + dL1[rr * 2 + 0]);
                const float ov = sigmoidf_(dH1[rr * 2 + 1] + dL1[rr * 2 + 1]);
                const float cn = fmaf(fv, c_s[r * CSTRN + U], iv * gv);
                c_s[r * CSTRN + U] = cn;
                const float hv = ov * tanhf_(cn);
                *(__half*)(an + r * ASTR + U * 2) = __float2half(hv);
                h32_s[r * CSTRN + U] = hv;   // fp32 copy for out-projection
            }
        } // cc

        __syncthreads();   // h_new (A[par^1]) + h32 complete

        if (tid < 128) {
            // out[t] = h_t @ w_out^T + b_out, from fp32 h copy
            const float* hp = h32_s + opr * CSTRN;
            float s0 = 0.f, s1 = 0.f;
#pragma unroll 4
            for (int u = 0; u < HID; u += 2) {
                s0 = fmaf(hp[u],     wout0[u],     s0);
                s1 = fmaf(hp[u + 1], wout0[u + 1], s1);
            }
            out[((size_t)t * NBATCH + rowg + opr) * 2 + (tid & 1)] = s0 + s1 + boutv;
        } else {
            // stage x for step t+1 (xs index = t); extra load at t=19 harmless
            x_s[tid - 128] = obs[((size_t)t * NBATCH + rowg) * 2 + (tid - 128)];
        }
        // x_s / buffer visibility for next step covered by chunk-0 top barrier
    } // t
}

extern "C" void kernel_launch(void* const* d_in, const int* in_sizes, int n_in,
                              void* d_out, int out_size)
{
    const float* obs   = (const float*)d_in[0];
    const float* h0    = (const float*)d_in[1];
    const float* w_ih  = (const float*)d_in[2];
    const float* w_hh  = (const float*)d_in[3];
    const float* b_ih  = (const float*)d_in[4];
    const float* b_hh  = (const float*)d_in[5];
    const float* w_out = (const float*)d_in[6];
    const float* b_out = (const float*)d_in[7];
    float* out = (float*)d_out;

    prepack<<<1200, 256>>>(w_hh);

    cudaFuncSetAttribute(lstm_mma, cudaFuncAttributeMaxDynamicSharedMemorySize,
                         SMEM_BYTES);
    lstm_mma<<<NBATCH / MROWS, TPB, SMEM_BYTES>>>(obs, h0, w_ih, b_ih, b_hh,
                                                  w_out, b_out, out);
}

// round 15
// speedup vs baseline: 1.6625x; 1.2851x over previous
#include <cuda_runtime.h>
#include <cuda_fp16.h>
#include <math.h>
#include <stdint.h>

#define TPB    256
#define MROWS  128
#define HID    192
#define TSTEPS 20
#define NBATCH 131072
#define NCH    24        // gate chunks of 32
#define KSTEPS 12
#define ASTR   400       // A/B row stride in bytes (200 fp16) -> conflict-free ldmatrix

// SMEM byte offsets
#define A_OFF    0       // A: [par=2][128 rows][ASTR] fp16
#define APAR     51200
#define B_OFF    102400  // [stage=2][term=2][32 n][ASTR] fp16
#define BSTAGE   25600
#define BTERM    12800
#define WIH_OFF  153600  // [768][2] f32
#define BIAS_OFF 159744  // [768] f32
#define WOUT_OFF 162816  // [2][192] f32
#define X_OFF    164352  // [128][2] f32
#define SMEM_BYTES 165376

// prepacked B: [24 chunks][2 terms][32 n][200 k] fp16 (term0=hi, term1=lo)
__device__ uint4 g_bpack[38400];   // 614400 B
// c state in gmem scratch (100.7 MB) — t=0 never reads it, so replays are
// deterministic; loads prefetched a full chunk ahead of use.
__device__ float g_c[(size_t)NBATCH * HID];

// ---------------- helpers ----------------
__device__ __forceinline__ uint32_t smem_u32(const void* p) {
    uint32_t a;
    asm("{ .reg .u64 t; cvta.to.shared.u64 t, %1; cvt.u32.u64 %0, t; }"
        : "=r"(a) : "l"(p));
    return a;
}
__device__ __forceinline__ void ldmx4(uint32_t* r, uint32_t addr) {
    asm volatile("ldmatrix.sync.aligned.m8n8.x4.shared.b16 {%0,%1,%2,%3}, [%4];"
                 : "=r"(r[0]), "=r"(r[1]), "=r"(r[2]), "=r"(r[3]) : "r"(addr));
}
__device__ __forceinline__ void mma16816(float* c, const uint32_t* a,
                                         uint32_t b0, uint32_t b1) {
    asm volatile(
        "mma.sync.aligned.m16n8k16.row.col.f32.f16.f16.f32 "
        "{%0,%1,%2,%3}, {%4,%5,%6,%7}, {%8,%9}, {%0,%1,%2,%3};"
        : "+f"(c[0]), "+f"(c[1]), "+f"(c[2]), "+f"(c[3])
        : "r"(a[0]), "r"(a[1]), "r"(a[2]), "r"(a[3]), "r"(b0), "r"(b1));
}
__device__ __forceinline__ void cpasync16(uint32_t dst, const void* src) {
    asm volatile("cp.async.cg.shared.global [%0], [%1], 16;"
                 :: "r"(dst), "l"(src));
}
__device__ __forceinline__ float sigmoidf_(float x) {
    float e = __expf(-x);
    return __fdividef(1.f, 1.f + e);
}
__device__ __forceinline__ float tanhf_(float x) {
    float ax = fabsf(x);
    float e  = __expf(-2.f * ax);
    float r  = (1.f - e) * __fdividef(1.f, 1.f + e);
    return copysignf(r, x);
}

// ---------------- prepack: w_hh -> unit-paired fp16 hi/lo tiles ----------------
// Column n (0..31) of chunk cc: U = cc*8 + (n>>4)*4 + ((n&7)>>1),
// g = (n&1) + 2*((n>>3)&1), grow = g*192 + U.
__global__ void prepack(const float* __restrict__ w_hh) {
    const int e   = blockIdx.x * 256 + threadIdx.x;    // 1200 blocks -> 307200
    const int k   = e % 200;
    const int n   = (e / 200) & 31;
    const int cc  = e / 12800;
    const int np  = n & 15;
    const int U   = cc * 8 + (n >> 4) * 4 + ((np & 7) >> 1);
    const int g   = (np & 1) + 2 * (np >> 3);
    const int grow = g * HID + U;
    const float v = (k < HID) ? w_hh[(size_t)grow * HID + k] : 0.f;
    const __half hi = __float2half(v);
    const int term = (e / 6400) & 1;
    ((__half*)g_bpack)[e] = term ? __float2half(v - __half2float(hi)) : hi;
}

// ---------------- main kernel ----------------
__global__ void __launch_bounds__(TPB, 1)
lstm_mma(const float* __restrict__ obs,    // [20][N][2]
         const float* __restrict__ h0,     // [N][192]
         const float* __restrict__ w_ih,   // [768][2]
         const float* __restrict__ b_ih,   // [768]
         const float* __restrict__ b_hh,   // [768]
         const float* __restrict__ w_out,  // [2][192]
         const float* __restrict__ b_out,  // [2]
         float* __restrict__ out)          // [20][N][2]
{
    extern __shared__ char sm[];
    const uint32_t smb = smem_u32(sm);
    float* wih_s  = (float*)(sm + WIH_OFF);
    float* bias_s = (float*)(sm + BIAS_OFF);
    float* wout_s = (float*)(sm + WOUT_OFF);
    float* x_s    = (float*)(sm + X_OFF);

    const int tid  = threadIdx.x;
    const int lane = tid & 31;
    const int wid  = tid >> 5;
    const int rg   = wid & 3;              // rowgroup: rows rg*32..+31 (2 m16 tiles)
    const int cg   = wid >> 2;             // colgroup within 32-col chunk
    const size_t rowg = (size_t)blockIdx.x * MROWS;

    // ---- one-time staging ----
    for (int i = tid; i < MROWS * HID; i += TPB) {       // h0 -> A[par=0] fp16
        const int r = i / HID, k = i - r * HID;
        *(__half*)(sm + A_OFF + r * ASTR + k * 2) =
            __float2half(h0[(rowg + r) * HID + k]);
    }
    for (int i = tid; i < 768; i += TPB) {
        wih_s[2 * i]     = w_ih[2 * i];
        wih_s[2 * i + 1] = w_ih[2 * i + 1];
        bias_s[i]        = b_ih[i] + b_hh[i];
    }
    for (int i = tid; i < 384; i += TPB) wout_s[i] = w_out[i];
    x_s[tid] = obs[rowg * 2 + tid];        // t=0 uses obs[0]; 256 = 128 rows x 2
    const float boutv = b_out[tid & 1];

    // prefetch chunk 0 -> stage 0
    {
        const uint4* src = g_bpack;
        const uint32_t dst = smb + B_OFF;
        for (int i = tid; i < 1600; i += TPB) cpasync16(dst + i * 16, src + i);
        asm volatile("cp.async.commit_group;" ::: "memory");
    }

    // order cooperative staging before any A-fragment reads
    __syncthreads();

    // per-lane ldmatrix offsets (bytes)
    const uint32_t a_lane_off =
        (uint32_t)((rg * 32 + (lane & 7) + ((lane >> 3) & 1) * 8) * ASTR
                   + ((lane >> 4) & 1) * 16);
    const uint32_t b_lane_off =
        (uint32_t)((cg * 16 + ((lane >> 4) & 1) * 8 + (lane & 7)) * ASTR
                   + ((lane >> 3) & 1) * 16);
    const int ulan = lane & 3;             // unit-within-4 this thread owns
    const int r0   = rg * 32 + (lane >> 2);

    const float* wout0 = wout_s + (tid & 1) * HID;   // for out-projection
    const int opr = tid >> 1;                        // out-projection row (0..127)

    for (int t = 0; t < TSTEPS; t++) {
        const int par = t & 1;

        // ---- persistent A fragments: 2 M-tiles x 12 ksteps (fp16, 96 regs) ----
        const uint32_t a_p = smb + A_OFF + par * APAR + a_lane_off;
        uint32_t af[2][KSTEPS][4];
#pragma unroll
        for (int mt = 0; mt < 2; mt++)
#pragma unroll
            for (int ks = 0; ks < KSTEPS; ks++)
                ldmx4(af[mt][ks], a_p + mt * (16 * ASTR) + ks * 32);

        char* an = sm + A_OFF + (par ^ 1) * APAR;   // h_new fp16 destination

#pragma unroll 1
        for (int cc = 0; cc < NCH; cc++) {
            asm volatile("cp.async.wait_group 0;" ::: "memory");
            __syncthreads();   // B stage ready; x_s visible (chunk 0)

            const int U = cc * 8 + cg * 4 + ulan;

            // prefetch c for this chunk's 4 cells EARLY (covered by K sweep)
            float cold[2][2];
            if (t == 0) {
                cold[0][0] = cold[0][1] = cold[1][0] = cold[1][1] = 0.f;
            } else {
#pragma unroll
                for (int mt = 0; mt < 2; mt++)
#pragma unroll
                    for (int rr = 0; rr < 2; rr++)
                        cold[mt][rr] =
                            g_c[(rowg + r0 + mt * 16 + rr * 8) * (size_t)HID + U];
            }

            // prefetch next B chunk into the other stage
            {
                const int nc = (cc + 1 == NCH) ? 0 : cc + 1;
                const uint4* src = g_bpack + nc * 1600;
                const uint32_t dst = smb + B_OFF + ((cc + 1) & 1) * BSTAGE;
                for (int i = tid; i < 1600; i += TPB) cpasync16(dst + i * 16, src + i);
                asm volatile("cp.async.commit_group;" ::: "memory");
            }

            // accumulator init: dH = bias + x@w_ih^T; dL = 0.  [mt][n8][4]
            float dH[2][2][4], dL[2][2][4];
#pragma unroll
            for (int mt = 0; mt < 2; mt++) {
                const int ra = r0 + mt * 16, rb = ra + 8;
                const float x00 = x_s[ra * 2], x01 = x_s[ra * 2 + 1];
                const float x10 = x_s[rb * 2], x11 = x_s[rb * 2 + 1];
#pragma unroll
                for (int n8 = 0; n8 < 2; n8++)
#pragma unroll
                    for (int g = 0; g < 2; g++) {
                        const int grow = (n8 * 2 + g) * HID + U;
                        const float w0 = wih_s[2 * grow], w1 = wih_s[2 * grow + 1];
                        const float bb = bias_s[grow];
                        dH[mt][n8][g]     = fmaf(x00, w0, fmaf(x01, w1, bb));
                        dH[mt][n8][g + 2] = fmaf(x10, w0, fmaf(x11, w1, bb));
                        dL[mt][n8][g]     = 0.f;
                        dL[mt][n8][g + 2] = 0.f;
                    }
            }

            // K sweep: each B fragment pair feeds 8 MMAs (2 M-tiles x 2 n8 x 2 terms)
            const uint32_t bb0 = smb + B_OFF + (cc & 1) * BSTAGE + b_lane_off;
#pragma unroll
            for (int ks = 0; ks < KSTEPS; ks++) {
                uint32_t bh[4], bl[4];
                ldmx4(bh, bb0 + ks * 32);
                ldmx4(bl, bb0 + BTERM + ks * 32);
#pragma unroll
                for (int mt = 0; mt < 2; mt++) {
                    mma16816(dH[mt][0], af[mt][ks], bh[0], bh[1]);
                    mma16816(dH[mt][1], af[mt][ks], bh[2], bh[3]);
                    mma16816(dL[mt][0], af[mt][ks], bl[0], bl[1]);
                    mma16816(dL[mt][1], af[mt][ks], bl[2], bl[3]);
                }
            }

            // epilogue: 4 cells (2 M-tiles x 2 rows), unit U
#pragma unroll
            for (int mt = 0; mt < 2; mt++)
#pragma unroll
                for (int rr = 0; rr < 2; rr++) {
                    const int r = r0 + mt * 16 + rr * 8;
                    const float iv = sigmoidf_(dH[mt][0][rr*2+0] + dL[mt][0][rr*2+0]);
                    const float fv = sigmoidf_(dH[mt][0][rr*2+1] + dL[mt][0][rr*2+1]);
                    const float gv = tanhf_  (dH[mt][1][rr*2+0] + dL[mt][1][rr*2+0]);
                    const float ov = sigmoidf_(dH[mt][1][rr*2+1] + dL[mt][1][rr*2+1]);
                    const float cn = fmaf(fv, cold[mt][rr], iv * gv);
                    g_c[(rowg + r) * (size_t)HID + U] = cn;
                    *(__half*)(an + r * ASTR + U * 2) =
                        __float2half(ov * tanhf_(cn));
                }
        } // cc

        __syncthreads();   // h_new (A[par^1]) complete

        // out[t] = h_t @ w_out^T + b_out, reading the fp16 h image
        {
            const __half2* ph = (const __half2*)(an + opr * ASTR);
            float s0 = 0.f, s1 = 0.f;
#pragma unroll 4
            for (int u2 = 0; u2 < 96; u2++) {
                const float2 hh = __half22float2(ph[u2]);
                s0 = fmaf(hh.x, wout0[2 * u2],     s0);
                s1 = fmaf(hh.y, wout0[2 * u2 + 1], s1);
            }
            out[((size_t)t * NBATCH + rowg + opr) * 2 + (tid & 1)] = s0 + s1 + boutv;
        }
        // stage x for step t+1 (xs index = t); extra load at t=19 harmless.
        // Safe: all reads of x_s in step t ended before the barrier above;
        // next step's reads are ordered by chunk-0's top barrier.
        x_s[tid] = obs[((size_t)t * NBATCH + rowg) * 2 + tid];
    } // t
}

extern "C" void kernel_launch(void* const* d_in, const int* in_sizes, int n_in,
                              void* d_out, int out_size)
{
    const float* obs   = (const float*)d_in[0];
    const float* h0    = (const float*)d_in[1];
    const float* w_ih  = (const float*)d_in[2];
    const float* w_hh  = (const float*)d_in[3];
    const float* b_ih  = (const float*)d_in[4];
    const float* b_hh  = (const float*)d_in[5];
    const float* w_out = (const float*)d_in[6];
    const float* b_out = (const float*)d_in[7];
    float* out = (float*)d_out;

    prepack<<<1200, 256>>>(w_hh);

    cudaFuncSetAttribute(lstm_mma, cudaFuncAttributeMaxDynamicSharedMemorySize,
                         SMEM_BYTES);
    lstm_mma<<<NBATCH / MROWS, TPB, SMEM_BYTES>>>(obs, h0, w_ih, b_ih, b_hh,
                                                  w_out, b_out, out);
}

// round 16
// speedup vs baseline: 2.2785x; 1.3705x over previous
#include <cuda_runtime.h>
#include <cuda_fp16.h>
#include <math.h>
#include <stdint.h>

#define TPB    256
#define MROWS  128
#define HID    192
#define TSTEPS 20
#define NBATCH 131072
#define NCH    24        // gate chunks of 32
#define KSTEPS 12
#define ASTR   400       // A/B row stride in bytes (200 fp16) -> conflict-free ldmatrix

// SMEM byte offsets
#define A_OFF    0       // A: [par=2][128 rows][ASTR] fp16
#define APAR     51200
#define B_OFF    102400  // [stage=2][32 n][ASTR] fp16 (single term)
#define BSTAGE   12800
#define WIH_OFF  128000  // [768][2] f32
#define BIAS_OFF 134144  // [768] f32
#define WOUT_OFF 137216  // [2][192] f32
#define X_OFF    138752  // [128][2] f32
#define SMEM_BYTES 139776

// prepacked B: [24 chunks][32 n][200 k] fp16 (single hi term)
__device__ uint4 g_bpack[19200];   // 307200 B
// c state in gmem scratch — t=0 never reads it, so replays are deterministic;
// loads prefetched a full K-sweep ahead of use.
__device__ float g_c[(size_t)NBATCH * HID];

// ---------------- helpers ----------------
__device__ __forceinline__ uint32_t smem_u32(const void* p) {
    uint32_t a;
    asm("{ .reg .u64 t; cvta.to.shared.u64 t, %1; cvt.u32.u64 %0, t; }"
        : "=r"(a) : "l"(p));
    return a;
}
__device__ __forceinline__ void ldmx4(uint32_t* r, uint32_t addr) {
    asm volatile("ldmatrix.sync.aligned.m8n8.x4.shared.b16 {%0,%1,%2,%3}, [%4];"
                 : "=r"(r[0]), "=r"(r[1]), "=r"(r[2]), "=r"(r[3]) : "r"(addr));
}
__device__ __forceinline__ void mma16816(float* c, const uint32_t* a,
                                         uint32_t b0, uint32_t b1) {
    asm volatile(
        "mma.sync.aligned.m16n8k16.row.col.f32.f16.f16.f32 "
        "{%0,%1,%2,%3}, {%4,%5,%6,%7}, {%8,%9}, {%0,%1,%2,%3};"
        : "+f"(c[0]), "+f"(c[1]), "+f"(c[2]), "+f"(c[3])
        : "r"(a[0]), "r"(a[1]), "r"(a[2]), "r"(a[3]), "r"(b0), "r"(b1));
}
__device__ __forceinline__ void cpasync16(uint32_t dst, const void* src) {
    asm volatile("cp.async.cg.shared.global [%0], [%1], 16;"
                 :: "r"(dst), "l"(src));
}
__device__ __forceinline__ float sigmoidf_(float x) {
    float e = __expf(-x);
    return __fdividef(1.f, 1.f + e);
}
__device__ __forceinline__ float tanhf_(float x) {
    float ax = fabsf(x);
    float e  = __expf(-2.f * ax);
    float r  = (1.f - e) * __fdividef(1.f, 1.f + e);
    return copysignf(r, x);
}

// ---------------- prepack: w_hh -> unit-paired fp16 tiles (single term) -------
// Column n (0..31) of chunk cc: U = cc*8 + (n>>4)*4 + ((n&7)>>1),
// g = (n&1) + 2*((n>>3)&1), grow = g*192 + U.
__global__ void prepack(const float* __restrict__ w_hh) {
    const int e   = blockIdx.x * 256 + threadIdx.x;    // 600 blocks -> 153600
    const int k   = e % 200;
    const int n   = (e / 200) & 31;
    const int cc  = e / 6400;
    const int np  = n & 15;
    const int U   = cc * 8 + (n >> 4) * 4 + ((np & 7) >> 1);
    const int g   = (np & 1) + 2 * (np >> 3);
    const int grow = g * HID + U;
    const float v = (k < HID) ? w_hh[(size_t)grow * HID + k] : 0.f;
    ((__half*)g_bpack)[e] = __float2half(v);
}

// ---------------- main kernel ----------------
__global__ void __launch_bounds__(TPB, 1)
lstm_mma(const float* __restrict__ obs,    // [20][N][2]
         const float* __restrict__ h0,     // [N][192]
         const float* __restrict__ w_ih,   // [768][2]
         const float* __restrict__ b_ih,   // [768]
         const float* __restrict__ b_hh,   // [768]
         const float* __restrict__ w_out,  // [2][192]
         const float* __restrict__ b_out,  // [2]
         float* __restrict__ out)          // [20][N][2]
{
    extern __shared__ char sm[];
    const uint32_t smb = smem_u32(sm);
    float* wih_s  = (float*)(sm + WIH_OFF);
    float* bias_s = (float*)(sm + BIAS_OFF);
    float* wout_s = (float*)(sm + WOUT_OFF);
    float* x_s    = (float*)(sm + X_OFF);

    const int tid  = threadIdx.x;
    const int lane = tid & 31;
    const int wid  = tid >> 5;
    const int rg   = wid & 3;              // rowgroup: rows rg*32..+31 (2 m16 tiles)
    const int cg   = wid >> 2;             // colgroup within 32-col chunk
    const size_t rowg = (size_t)blockIdx.x * MROWS;

    // ---- one-time staging ----
    for (int i = tid; i < MROWS * HID; i += TPB) {       // h0 -> A[par=0] fp16
        const int r = i / HID, k = i - r * HID;
        *(__half*)(sm + A_OFF + r * ASTR + k * 2) =
            __float2half(h0[(rowg + r) * HID + k]);
    }
    for (int i = tid; i < 768; i += TPB) {
        wih_s[2 * i]     = w_ih[2 * i];
        wih_s[2 * i + 1] = w_ih[2 * i + 1];
        bias_s[i]        = b_ih[i] + b_hh[i];
    }
    for (int i = tid; i < 384; i += TPB) wout_s[i] = w_out[i];
    x_s[tid] = obs[rowg * 2 + tid];        // t=0 uses obs[0]; 256 = 128 rows x 2
    const float boutv = b_out[tid & 1];

    // prefetch chunk 0 -> stage 0 (800 uint4 = 12800 B)
    {
        const uint4* src = g_bpack;
        const uint32_t dst = smb + B_OFF;
        for (int i = tid; i < 800; i += TPB) cpasync16(dst + i * 16, src + i);
        asm volatile("cp.async.commit_group;" ::: "memory");
    }

    // order cooperative staging before any A-fragment reads
    __syncthreads();

    // per-lane ldmatrix offsets (bytes)
    const uint32_t a_lane_off =
        (uint32_t)((rg * 32 + (lane & 7) + ((lane >> 3) & 1) * 8) * ASTR
                   + ((lane >> 4) & 1) * 16);
    const uint32_t b_lane_off =
        (uint32_t)((cg * 16 + ((lane >> 4) & 1) * 8 + (lane & 7)) * ASTR
                   + ((lane >> 3) & 1) * 16);
    const int ulan = lane & 3;             // unit-within-4 this thread owns
    const int r0   = rg * 32 + (lane >> 2);

    const float* wout0 = wout_s + (tid & 1) * HID;   // for out-projection
    const int opr = tid >> 1;                        // out-projection row (0..127)

    for (int t = 0; t < TSTEPS; t++) {
        const int par = t & 1;

        // ---- persistent A fragments: 2 M-tiles x 12 ksteps (fp16, 96 regs) ----
        const uint32_t a_p = smb + A_OFF + par * APAR + a_lane_off;
        uint32_t af[2][KSTEPS][4];
#pragma unroll
        for (int mt = 0; mt < 2; mt++)
#pragma unroll
            for (int ks = 0; ks < KSTEPS; ks++)
                ldmx4(af[mt][ks], a_p + mt * (16 * ASTR) + ks * 32);

        char* an = sm + A_OFF + (par ^ 1) * APAR;   // h_new fp16 destination

#pragma unroll 1
        for (int cc = 0; cc < NCH; cc++) {
            asm volatile("cp.async.wait_group 0;" ::: "memory");
            __syncthreads();   // B stage ready; x_s visible (chunk 0)

            const int U = cc * 8 + cg * 4 + ulan;

            // prefetch c for this chunk's 4 cells EARLY (covered by K sweep)
            float cold[2][2];
            if (t == 0) {
                cold[0][0] = cold[0][1] = cold[1][0] = cold[1][1] = 0.f;
            } else {
#pragma unroll
                for (int mt = 0; mt < 2; mt++)
#pragma unroll
                    for (int rr = 0; rr < 2; rr++)
                        cold[mt][rr] =
                            g_c[(rowg + r0 + mt * 16 + rr * 8) * (size_t)HID + U];
            }

            // prefetch next B chunk into the other stage
            {
                const int nc = (cc + 1 == NCH) ? 0 : cc + 1;
                const uint4* src = g_bpack + nc * 800;
                const uint32_t dst = smb + B_OFF + ((cc + 1) & 1) * BSTAGE;
                for (int i = tid; i < 800; i += TPB) cpasync16(dst + i * 16, src + i);
                asm volatile("cp.async.commit_group;" ::: "memory");
            }

            // accumulator init: dH = bias + x@w_ih^T.  [mt][n8][4]
            float dH[2][2][4];
#pragma unroll
            for (int mt = 0; mt < 2; mt++) {
                const int ra = r0 + mt * 16, rb = ra + 8;
                const float x00 = x_s[ra * 2], x01 = x_s[ra * 2 + 1];
                const float x10 = x_s[rb * 2], x11 = x_s[rb * 2 + 1];
#pragma unroll
                for (int n8 = 0; n8 < 2; n8++)
#pragma unroll
                    for (int g = 0; g < 2; g++) {
                        const int grow = (n8 * 2 + g) * HID + U;
                        const float w0 = wih_s[2 * grow], w1 = wih_s[2 * grow + 1];
                        const float bb = bias_s[grow];
                        dH[mt][n8][g]     = fmaf(x00, w0, fmaf(x01, w1, bb));
                        dH[mt][n8][g + 2] = fmaf(x10, w0, fmaf(x11, w1, bb));
                    }
            }

            // K sweep: 1 B ldm feeds 4 MMAs (2 M-tiles x 2 n8), 4 indep chains
            const uint32_t bb0 = smb + B_OFF + (cc & 1) * BSTAGE + b_lane_off;
#pragma unroll
            for (int ks = 0; ks < KSTEPS; ks++) {
                uint32_t bh[4];
                ldmx4(bh, bb0 + ks * 32);
#pragma unroll
                for (int mt = 0; mt < 2; mt++) {
                    mma16816(dH[mt][0], af[mt][ks], bh[0], bh[1]);
                    mma16816(dH[mt][1], af[mt][ks], bh[2], bh[3]);
                }
            }

            // epilogue: 4 cells (2 M-tiles x 2 rows), unit U
#pragma unroll
            for (int mt = 0; mt < 2; mt++)
#pragma unroll
                for (int rr = 0; rr < 2; rr++) {
                    const int r = r0 + mt * 16 + rr * 8;
                    const float iv = sigmoidf_(dH[mt][0][rr * 2 + 0]);
                    const float fv = sigmoidf_(dH[mt][0][rr * 2 + 1]);
                    const float gv = tanhf_  (dH[mt][1][rr * 2 + 0]);
                    const float ov = sigmoidf_(dH[mt][1][rr * 2 + 1]);
                    const float cn = fmaf(fv, cold[mt][rr], iv * gv);
                    g_c[(rowg + r) * (size_t)HID + U] = cn;
                    *(__half*)(an + r * ASTR + U * 2) =
                        __float2half(ov * tanhf_(cn));
                }
        } // cc

        __syncthreads();   // h_new (A[par^1]) complete

        // out[t] = h_t @ w_out^T + b_out, reading the fp16 h image
        {
            const __half2* ph = (const __half2*)(an + opr * ASTR);
            float s0 = 0.f, s1 = 0.f;
#pragma unroll 4
            for (int u2 = 0; u2 < 96; u2++) {
                const float2 hh = __half22float2(ph[u2]);
                s0 = fmaf(hh.x, wout0[2 * u2],     s0);
                s1 = fmaf(hh.y, wout0[2 * u2 + 1], s1);
            }
            out[((size_t)t * NBATCH + rowg + opr) * 2 + (tid & 1)] = s0 + s1 + boutv;
        }
        // stage x for step t+1 (xs index = t); extra load at t=19 harmless.
        x_s[tid] = obs[((size_t)t * NBATCH + rowg) * 2 + tid];
    } // t
}

extern "C" void kernel_launch(void* const* d_in, const int* in_sizes, int n_in,
                              void* d_out, int out_size)
{
    const float* obs   = (const float*)d_in[0];
    const float* h0    = (const float*)d_in[1];
    const float* w_ih  = (const float*)d_in[2];
    const float* w_hh  = (const float*)d_in[3];
    const float* b_ih  = (const float*)d_in[4];
    const float* b_hh  = (const float*)d_in[5];
    const float* w_out = (const float*)d_in[6];
    const float* b_out = (const float*)d_in[7];
    float* out = (float*)d_out;

    prepack<<<600, 256>>>(w_hh);

    cudaFuncSetAttribute(lstm_mma, cudaFuncAttributeMaxDynamicSharedMemorySize,
                         SMEM_BYTES);
    lstm_mma<<<NBATCH / MROWS, TPB, SMEM_BYTES>>>(obs, h0, w_ih, b_ih, b_hh,
                                                  w_out, b_out, out);
}

// round 17
// speedup vs baseline: 2.4144x; 1.0596x over previous
#include <cuda_runtime.h>
#include <cuda_fp16.h>
#include <math.h>
#include <stdint.h>

#define TPB    256
#define MROWS  128
#define HID    192
#define TSTEPS 20
#define NBATCH 131072
#define NCH    24        // gate chunks of 32
#define KSTEPS 12
#define ASTR   400       // A/B row stride in bytes (200 fp16) -> conflict-free ldmatrix

// SMEM byte offsets (single A buffer -> 88.6 KB total -> 2 CTAs/SM)
#define A_OFF    0       // A: [128 rows][ASTR] fp16 (in-place h update)
#define B_OFF    51200   // [stage=2][32 n][ASTR] fp16 (single term)
#define BSTAGE   12800
#define WIH_OFF  76800   // [768][2] f32
#define BIAS_OFF 82944   // [768] f32
#define WOUT_OFF 86016   // [2][192] f32
#define X_OFF    87552   // [128][2] f32
#define SMEM_BYTES 88576

// prepacked B: [24 chunks][32 n][200 k] fp16 (single hi term)
__device__ uint4 g_bpack[19200];   // 307200 B
// c state in gmem scratch — t=0 never reads it, so replays are deterministic;
// loads prefetched a full K-sweep ahead of use.
__device__ float g_c[(size_t)NBATCH * HID];

// ---------------- helpers ----------------
__device__ __forceinline__ uint32_t smem_u32(const void* p) {
    uint32_t a;
    asm("{ .reg .u64 t; cvta.to.shared.u64 t, %1; cvt.u32.u64 %0, t; }"
        : "=r"(a) : "l"(p));
    return a;
}
__device__ __forceinline__ void ldmx4(uint32_t* r, uint32_t addr) {
    asm volatile("ldmatrix.sync.aligned.m8n8.x4.shared.b16 {%0,%1,%2,%3}, [%4];"
                 : "=r"(r[0]), "=r"(r[1]), "=r"(r[2]), "=r"(r[3]) : "r"(addr));
}
__device__ __forceinline__ void mma16816(float* c, const uint32_t* a,
                                         uint32_t b0, uint32_t b1) {
    asm volatile(
        "mma.sync.aligned.m16n8k16.row.col.f32.f16.f16.f32 "
        "{%0,%1,%2,%3}, {%4,%5,%6,%7}, {%8,%9}, {%0,%1,%2,%3};"
        : "+f"(c[0]), "+f"(c[1]), "+f"(c[2]), "+f"(c[3])
        : "r"(a[0]), "r"(a[1]), "r"(a[2]), "r"(a[3]), "r"(b0), "r"(b1));
}
__device__ __forceinline__ void cpasync16(uint32_t dst, const void* src) {
    asm volatile("cp.async.cg.shared.global [%0], [%1], 16;"
                 :: "r"(dst), "l"(src));
}
__device__ __forceinline__ float sigmoidf_(float x) {
    float e = __expf(-x);
    return __fdividef(1.f, 1.f + e);
}
__device__ __forceinline__ float tanhf_(float x) {
    float ax = fabsf(x);
    float e  = __expf(-2.f * ax);
    float r  = (1.f - e) * __fdividef(1.f, 1.f + e);
    return copysignf(r, x);
}

// ---------------- prepack: w_hh -> unit-paired fp16 tiles (single term) -------
// Column n (0..31) of chunk cc: U = cc*8 + (n>>4)*4 + ((n&7)>>1),
// g = (n&1) + 2*((n>>3)&1), grow = g*192 + U.
__global__ void prepack(const float* __restrict__ w_hh) {
    const int e   = blockIdx.x * 256 + threadIdx.x;    // 600 blocks -> 153600
    const int k   = e % 200;
    const int n   = (e / 200) & 31;
    const int cc  = e / 6400;
    const int np  = n & 15;
    const int U   = cc * 8 + (n >> 4) * 4 + ((np & 7) >> 1);
    const int g   = (np & 1) + 2 * (np >> 3);
    const int grow = g * HID + U;
    const float v = (k < HID) ? w_hh[(size_t)grow * HID + k] : 0.f;
    ((__half*)g_bpack)[e] = __float2half(v);
}

// ---------------- main kernel ----------------
__global__ void __launch_bounds__(TPB, 2)
lstm_mma(const float* __restrict__ obs,    // [20][N][2]
         const float* __restrict__ h0,     // [N][192]
         const float* __restrict__ w_ih,   // [768][2]
         const float* __restrict__ b_ih,   // [768]
         const float* __restrict__ b_hh,   // [768]
         const float* __restrict__ w_out,  // [2][192]
         const float* __restrict__ b_out,  // [2]
         float* __restrict__ out)          // [20][N][2]
{
    extern __shared__ char sm[];
    const uint32_t smb = smem_u32(sm);
    float* wih_s  = (float*)(sm + WIH_OFF);
    float* bias_s = (float*)(sm + BIAS_OFF);
    float* wout_s = (float*)(sm + WOUT_OFF);
    float* x_s    = (float*)(sm + X_OFF);

    const int tid  = threadIdx.x;
    const int lane = tid & 31;
    const int wid  = tid >> 5;             // rowgroup 0..7: rows wid*16..+15
    const size_t rowg = (size_t)blockIdx.x * MROWS;

    // ---- one-time staging ----
    for (int i = tid; i < MROWS * HID; i += TPB) {       // h0 -> A fp16
        const int r = i / HID, k = i - r * HID;
        *(__half*)(sm + A_OFF + r * ASTR + k * 2) =
            __float2half(h0[(rowg + r) * HID + k]);
    }
    for (int i = tid; i < 768; i += TPB) {
        wih_s[2 * i]     = w_ih[2 * i];
        wih_s[2 * i + 1] = w_ih[2 * i + 1];
        bias_s[i]        = b_ih[i] + b_hh[i];
    }
    for (int i = tid; i < 384; i += TPB) wout_s[i] = w_out[i];
    x_s[tid] = obs[rowg * 2 + tid];        // t=0 uses obs[0]; 256 = 128 rows x 2
    const float boutv = b_out[tid & 1];

    // prefetch chunk 0 -> stage 0 (800 uint4 = 12800 B)
    {
        const uint4* src = g_bpack;
        const uint32_t dst = smb + B_OFF;
        for (int i = tid; i < 800; i += TPB) cpasync16(dst + i * 16, src + i);
        asm volatile("cp.async.commit_group;" ::: "memory");
    }

    // order cooperative staging before any A-fragment reads
    __syncthreads();

    // per-lane ldmatrix offsets (bytes)
    const uint32_t a_lane_off =
        (uint32_t)((wid * 16 + (lane & 7) + ((lane >> 3) & 1) * 8) * ASTR
                   + ((lane >> 4) & 1) * 16);
    const uint32_t b_lane_off =
        (uint32_t)(((((lane >> 4) & 1) * 8 + (lane & 7))) * ASTR
                   + ((lane >> 3) & 1) * 16);
    const int ulan = lane & 3;             // unit-within-4 this thread owns
    const int r0   = wid * 16 + (lane >> 2);

    const float* wout0 = wout_s + (tid & 1) * HID;   // for out-projection
    const int opr = tid >> 1;                        // out-projection row (0..127)

    for (int t = 0; t < TSTEPS; t++) {
        // ---- persistent A fragments: 1 M-tile x 12 ksteps (fp16, 48 regs) ----
        // Single A buffer: after these loads the SMEM image is dead until the
        // epilogues overwrite it in place (ordered by chunk-0's barrier).
        const uint32_t a_p = smb + A_OFF + a_lane_off;
        uint32_t af[KSTEPS][4];
#pragma unroll
        for (int ks = 0; ks < KSTEPS; ks++) ldmx4(af[ks], a_p + ks * 32);

        char* an = sm + A_OFF;             // h_new destination (in place)

#pragma unroll 1
        for (int cc = 0; cc < NCH; cc++) {
            asm volatile("cp.async.wait_group 0;" ::: "memory");
            __syncthreads();   // B stage ready; A-frag reads done; x_s visible

            // prefetch c for this chunk's 4 cells EARLY (covered by K sweep)
            float cold[2][2];
            if (t == 0) {
                cold[0][0] = cold[0][1] = cold[1][0] = cold[1][1] = 0.f;
            } else {
#pragma unroll
                for (int hf = 0; hf < 2; hf++)
#pragma unroll
                    for (int rr = 0; rr < 2; rr++)
                        cold[hf][rr] = g_c[(rowg + r0 + rr * 8) * (size_t)HID
                                           + cc * 8 + hf * 4 + ulan];
            }

            // prefetch next B chunk into the other stage
            {
                const int nc = (cc + 1 == NCH) ? 0 : cc + 1;
                const uint4* src = g_bpack + nc * 800;
                const uint32_t dst = smb + B_OFF + ((cc + 1) & 1) * BSTAGE;
                for (int i = tid; i < 800; i += TPB) cpasync16(dst + i * 16, src + i);
                asm volatile("cp.async.commit_group;" ::: "memory");
            }

            // accumulator init: dH = bias + x@w_ih^T.  [n8=4][4]
            // n8 0/1: units cc*8+ulan (gates i,f / g,o); n8 2/3: units +4
            float dH[4][4];
            {
                const float x00 = x_s[r0 * 2],       x01 = x_s[r0 * 2 + 1];
                const float x10 = x_s[(r0 + 8) * 2], x11 = x_s[(r0 + 8) * 2 + 1];
#pragma unroll
                for (int n8 = 0; n8 < 4; n8++) {
                    const int U = cc * 8 + (n8 >> 1) * 4 + ulan;
#pragma unroll
                    for (int g = 0; g < 2; g++) {
                        const int grow = ((n8 & 1) * 2 + g) * HID + U;
                        const float w0 = wih_s[2 * grow], w1 = wih_s[2 * grow + 1];
                        const float bb = bias_s[grow];
                        dH[n8][g]     = fmaf(x00, w0, fmaf(x01, w1, bb));
                        dH[n8][g + 2] = fmaf(x10, w0, fmaf(x11, w1, bb));
                    }
                }
            }

            // K sweep: warp covers all 32 chunk-cols (2 B ldm, 4 MMA per kstep)
            const uint32_t bb0 = smb + B_OFF + (cc & 1) * BSTAGE + b_lane_off;
#pragma unroll
            for (int ks = 0; ks < KSTEPS; ks++) {
                uint32_t b0[4], b1[4];
                ldmx4(b0, bb0 + ks * 32);                 // cols 0-15
                ldmx4(b1, bb0 + 16 * ASTR + ks * 32);     // cols 16-31
                mma16816(dH[0], af[ks], b0[0], b0[1]);
                mma16816(dH[1], af[ks], b0[2], b0[3]);
                mma16816(dH[2], af[ks], b1[0], b1[1]);
                mma16816(dH[3], af[ks], b1[2], b1[3]);
            }

            // epilogue: 4 cells (2 rows x 2 units)
#pragma unroll
            for (int hf = 0; hf < 2; hf++) {
                const int U = cc * 8 + hf * 4 + ulan;
#pragma unroll
                for (int rr = 0; rr < 2; rr++) {
                    const int r = r0 + rr * 8;
                    const float iv = sigmoidf_(dH[hf * 2 + 0][rr * 2 + 0]);
                    const float fv = sigmoidf_(dH[hf * 2 + 0][rr * 2 + 1]);
                    const float gv = tanhf_  (dH[hf * 2 + 1][rr * 2 + 0]);
                    const float ov = sigmoidf_(dH[hf * 2 + 1][rr * 2 + 1]);
                    const float cn = fmaf(fv, cold[hf][rr], iv * gv);
                    g_c[(rowg + r) * (size_t)HID + U] = cn;
                    *(__half*)(an + r * ASTR + U * 2) =
                        __float2half(ov * tanhf_(cn));
                }
            }
        } // cc

        __syncthreads();   // h_new (A in place) complete

        // out[t] = h_t @ w_out^T + b_out, reading the fp16 h image
        {
            const __half2* ph = (const __half2*)(an + opr * ASTR);
            float s0 = 0.f, s1 = 0.f;
#pragma unroll 4
            for (int u2 = 0; u2 < 96; u2++) {
                const float2 hh = __half22float2(ph[u2]);
                s0 = fmaf(hh.x, wout0[2 * u2],     s0);
                s1 = fmaf(hh.y, wout0[2 * u2 + 1], s1);
            }
            out[((size_t)t * NBATCH + rowg + opr) * 2 + (tid & 1)] = s0 + s1 + boutv;
        }
        // stage x for step t+1 (xs index = t); extra load at t=19 harmless.
        // Reads of x_s in step t all precede the barrier above; next step's
        // reads are ordered by chunk-0's top barrier.
        x_s[tid] = obs[((size_t)t * NBATCH + rowg) * 2 + tid];
    } // t
}

extern "C" void kernel_launch(void* const* d_in, const int* in_sizes, int n_in,
                              void* d_out, int out_size)
{
    const float* obs   = (const float*)d_in[0];
    const float* h0    = (const float*)d_in[1];
    const float* w_ih  = (const float*)d_in[2];
    const float* w_hh  = (const float*)d_in[3];
    const float* b_ih  = (const float*)d_in[4];
    const float* b_hh  = (const float*)d_in[5];
    const float* w_out = (const float*)d_in[6];
    const float* b_out = (const float*)d_in[7];
    float* out = (float*)d_out;

    prepack<<<600, 256>>>(w_hh);

    cudaFuncSetAttribute(lstm_mma, cudaFuncAttributeMaxDynamicSharedMemorySize,
                         SMEM_BYTES);
    lstm_mma<<<NBATCH / MROWS, TPB, SMEM_BYTES>>>(obs, h0, w_ih, b_ih, b_hh,
                                                  w_out, b_out, out);
}